// round 4
// baseline (speedup 1.0000x reference)
#include <cuda_runtime.h>
#include <math.h>

#define B_   8
#define T_   4096
#define D_   256
#define M_   1024
#define CTX_ 7
#define L_   4102
#define BT_  32768
#define KC_  1792

#define OFF_CP  8388608
#define OFF_PP  8388609
#define OFF_IND 8388610

__device__ float g_ctxn[B_ * D_ * L_];
__device__ float g_ctxout[B_ * D_ * T_];
__device__ float g_cur[BT_ * D_];
__device__ float g_wct[KC_ * D_];
__device__ float g_wt1[512 * D_];
__device__ float g_wt2[512 * D_];
__device__ float g_Et[D_ * M_];
__device__ float g_en[M_];
__device__ float g_ssum[B_];
__device__ float g_coef[B_];
__device__ int   g_idx[BT_];
__device__ int   g_hist[M_];
__device__ float g_avg[M_];

__device__ __forceinline__ float prelu_f(float v, float a) { return v >= 0.f ? v : a * v; }

// -log(u), accurate even under --use_fast_math (where __logf has ~3.6e-7 ABSOLUTE
// error near u=1, i.e. O(1) relative error on the tiny result).
__device__ __forceinline__ float neg_log_acc(float u) {
    if (u > 0.9f) {
        float d = 1.0f - u;  // exact (Sterbenz)
        return d * (1.f + d * (0.5f + d * (0.33333334f + d * (0.25f + d * (0.2f + d * 0.16666667f)))));
    }
    return -logf(u);
}

__global__ void k_init() {
    int i = threadIdx.x;
    g_hist[i] = 0; g_avg[i] = 0.f;
    if (i < B_) g_ssum[i] = 0.f;
}

__global__ void k_scale(const float* __restrict__ x) {
    int b = blockIdx.y;
    const float* xb = x + (size_t)b * T_ * D_;
    const int n = (T_ - 1) * D_;
    float s = 0.f;
    for (int i = blockIdx.x * blockDim.x + threadIdx.x; i < n; i += gridDim.x * blockDim.x) {
        float v = xb[i]; s += v * v;
    }
    __shared__ float red[256];
    red[threadIdx.x] = s; __syncthreads();
    for (int st = 128; st > 0; st >>= 1) {
        if (threadIdx.x < st) red[threadIdx.x] += red[threadIdx.x + st];
        __syncthreads();
    }
    if (threadIdx.x == 0) atomicAdd(&g_ssum[b], red[0]);
}

__global__ void k_coef(const int* __restrict__ epo_i) {
    int b = threadIdx.x;
    if (b >= B_) return;
    int ei = *epo_i;
    double ef = (ei >= 0 && ei <= 1000000) ? (double)ei : (double)__int_as_float(ei);
    double mean = (double)g_ssum[b] / (double)(D_ * L_);
    g_coef[b] = (float)(0.5 * exp2(-ef / 10.0) * sqrt(mean));
}

__global__ void k_prep(const float* __restrict__ wctx, const float* __restrict__ wf1,
                       const float* __restrict__ wf2, const float* __restrict__ emb) {
    int tid = blockIdx.x * blockDim.x + threadIdx.x;
    int stride = gridDim.x * blockDim.x;
    for (int i = tid; i < KC_ * D_; i += stride) {
        int c = i / D_, o = i % D_;
        g_wct[i] = wctx[o * KC_ + c];
    }
    for (int i = tid; i < 512 * D_; i += stride) {
        int c = i / D_, o = i % D_;
        g_wt1[i] = wf1[o * 512 + c];
        g_wt2[i] = wf2[o * 512 + c];
    }
    for (int i = tid; i < D_ * M_; i += stride) {
        int d = i / M_, m = i % M_;
        g_Et[i] = emb[m * D_ + d];
    }
    for (int m = tid; m < M_; m += stride) {
        double s = 0.0;
        for (int d = 0; d < D_; d++) { double v = (double)emb[m * D_ + d]; s += v * v; }
        g_en[m] = (float)s;
    }
}

__global__ void k_ctxn(const float* __restrict__ x, const float* __restrict__ noise) {
    __shared__ float xs[32][33];
    int b = blockIdx.z, bd = blockIdx.y * 32, bj = blockIdx.x * 32;
    int t = bj + threadIdx.y - CTX_;
    float v = 0.f;
    if (t >= 0 && t < T_ - 1)
        v = x[((size_t)b * T_ + t) * D_ + bd + threadIdx.x];
    xs[threadIdx.y][threadIdx.x] = v;
    __syncthreads();
    int j = bj + threadIdx.x;
    if (j < L_) {
        int d = bd + threadIdx.y;
        int off = (b * D_ + d) * L_ + j;
        g_ctxn[off] = xs[threadIdx.x][threadIdx.y] + g_coef[b] * noise[off];
    }
}

__global__ __launch_bounds__(256) void k_conv() {
    __shared__ float As[16][128];
    __shared__ float Bs[16][128];
    int b = blockIdx.z, bm = blockIdx.y * 128, bn = blockIdx.x * 128;
    int tid = threadIdx.x, tx = tid & 15, ty = tid >> 4;
    float acc[8][8];
#pragma unroll
    for (int i = 0; i < 8; i++)
#pragma unroll
        for (int j = 0; j < 8; j++) acc[i][j] = 0.f;
    const float* ctxn_b = g_ctxn + (size_t)b * D_ * L_;
    int lA_k = tid >> 4, lA_m = (tid & 15) << 3;
    int lB_n = tid & 127, lB_k0 = tid >> 7;
    for (int kk = 0; kk < KC_; kk += 16) {
        *(float4*)&As[lA_k][lA_m]     = *(const float4*)&g_wct[(kk + lA_k) * D_ + bm + lA_m];
        *(float4*)&As[lA_k][lA_m + 4] = *(const float4*)&g_wct[(kk + lA_k) * D_ + bm + lA_m + 4];
#pragma unroll
        for (int p = 0; p < 8; p++) {
            int k = lB_k0 + p * 2, c = kk + k;
            int ci = c / CTX_, ck = c - ci * CTX_;
            Bs[k][lB_n] = ctxn_b[ci * L_ + bn + lB_n + ck];
        }
        __syncthreads();
#pragma unroll
        for (int k = 0; k < 16; k++) {
            float a[8], bb[8];
            *(float4*)&a[0]  = *(float4*)&As[k][ty * 8];
            *(float4*)&a[4]  = *(float4*)&As[k][ty * 8 + 4];
            *(float4*)&bb[0] = *(float4*)&Bs[k][tx * 8];
            *(float4*)&bb[4] = *(float4*)&Bs[k][tx * 8 + 4];
#pragma unroll
            for (int i = 0; i < 8; i++)
#pragma unroll
                for (int j = 0; j < 8; j++) acc[i][j] = fmaf(a[i], bb[j], acc[i][j]);
        }
        __syncthreads();
    }
    float* outb = g_ctxout + (size_t)b * D_ * T_;
#pragma unroll
    for (int i = 0; i < 8; i++) {
        float* dst = &outb[(bm + ty * 8 + i) * T_ + bn + tx * 8];
        *(float4*)dst       = make_float4(acc[i][0], acc[i][1], acc[i][2], acc[i][3]);
        *(float4*)(dst + 4) = make_float4(acc[i][4], acc[i][5], acc[i][6], acc[i][7]);
    }
}

// WHICH==0: writes g_cur (device symbol, resolved in DEVICE code — never pass
// __device__ arrays as host-side kernel args!). WHICH==1: writes outp (d_out).
template<int WHICH>
__global__ __launch_bounds__(256) void k_fuse(const float* __restrict__ rowsrc,
                                              const float* __restrict__ pa,
                                              float* __restrict__ outp) {
    __shared__ float As[16][128];
    __shared__ float Bs[16][132];
    __shared__ int idxS[128];
    int tid = threadIdx.x;
    int tok0 = blockIdx.x * 128;
    int b = tok0 >> 12, t0 = tok0 & (T_ - 1);
    int bm = blockIdx.y * 128;
    int tx = tid & 15, ty = tid >> 4;
    if (WHICH == 1 && tid < 128) idxS[tid] = g_idx[tok0 + tid];
    float acc[8][8];
#pragma unroll
    for (int i = 0; i < 8; i++)
#pragma unroll
        for (int j = 0; j < 8; j++) acc[i][j] = 0.f;
    const float* ctxoutb = g_ctxout + (size_t)b * D_ * T_;
    const float* W = (WHICH == 0) ? g_wt1 : g_wt2;
    float* optr = (WHICH == 0) ? g_cur : outp;
    int lA_k = tid >> 4, lA_m = (tid & 15) << 3;
    int xn = tid >> 1, xk = (tid & 1) << 3;
    int cn_ = tid & 127, ck0 = tid >> 7;
    __syncthreads();
    for (int kk = 0; kk < 512; kk += 16) {
        *(float4*)&As[lA_k][lA_m]     = *(const float4*)&W[(kk + lA_k) * D_ + bm + lA_m];
        *(float4*)&As[lA_k][lA_m + 4] = *(const float4*)&W[(kk + lA_k) * D_ + bm + lA_m + 4];
        if (kk < 256) {
            const float* rp;
            if (WHICH == 0) rp = rowsrc + (size_t)(tok0 + xn) * D_ + kk + xk;
            else            rp = rowsrc + (size_t)idxS[xn] * D_ + kk + xk;
            float4 v0 = *(const float4*)rp;
            float4 v1 = *(const float4*)(rp + 4);
            Bs[xk + 0][xn] = v0.x; Bs[xk + 1][xn] = v0.y;
            Bs[xk + 2][xn] = v0.z; Bs[xk + 3][xn] = v0.w;
            Bs[xk + 4][xn] = v1.x; Bs[xk + 5][xn] = v1.y;
            Bs[xk + 6][xn] = v1.z; Bs[xk + 7][xn] = v1.w;
        } else {
#pragma unroll
            for (int p = 0; p < 8; p++) {
                int k = ck0 + p * 2;
                Bs[k][cn_] = ctxoutb[(kk - 256 + k) * T_ + t0 + cn_];
            }
        }
        __syncthreads();
#pragma unroll
        for (int k = 0; k < 16; k++) {
            float a[8], bb[8];
            *(float4*)&a[0]  = *(float4*)&As[k][ty * 8];
            *(float4*)&a[4]  = *(float4*)&As[k][ty * 8 + 4];
            *(float4*)&bb[0] = *(float4*)&Bs[k][tx * 8];
            *(float4*)&bb[4] = *(float4*)&Bs[k][tx * 8 + 4];
#pragma unroll
            for (int i = 0; i < 8; i++)
#pragma unroll
                for (int j = 0; j < 8; j++) acc[i][j] = fmaf(a[i], bb[j], acc[i][j]);
        }
        __syncthreads();
    }
    float av = *pa;
#pragma unroll
    for (int j = 0; j < 8; j++) {
        int tok = tok0 + tx * 8 + j;
        float* dst = &optr[(size_t)tok * D_ + bm + ty * 8];
        *(float4*)dst = make_float4(prelu_f(acc[0][j], av), prelu_f(acc[1][j], av),
                                    prelu_f(acc[2][j], av), prelu_f(acc[3][j], av));
        *(float4*)(dst + 4) = make_float4(prelu_f(acc[4][j], av), prelu_f(acc[5][j], av),
                                          prelu_f(acc[6][j], av), prelu_f(acc[7][j], av));
    }
}

// dist + softmax stats + argmaxes. Warp w owns rows r0+4w..+3; lane owns cols {lane+32j}.
// Chunked fp32 accumulation (8-term partials) keeps my-vs-reference divergence ~6e-6.
__global__ __launch_bounds__(256) void k_dist(const float* __restrict__ gu,
                                              float* __restrict__ dout) {
    __shared__ float Bs[8][1024];
    __shared__ float s_avg[1024];
    int tid = threadIdx.x;
    int w = tid >> 5, lane = tid & 31;
    int r0 = blockIdx.x * 32;
    int row0 = r0 + w * 4;

    for (int i = tid; i < M_; i += 256) s_avg[i] = 0.f;

    float cn[4];
#pragma unroll
    for (int i = 0; i < 4; i++) {
        const float* cr = g_cur + (size_t)(row0 + i) * D_;
        float s = 0.f;
#pragma unroll
        for (int q = 0; q < 8; q++) { float v = cr[lane + q * 32]; s += v * v; }
#pragma unroll
        for (int off = 16; off; off >>= 1) s += __shfl_xor_sync(0xffffffffu, s, off);
        cn[i] = s;
    }

    float acc[4][32];
#pragma unroll
    for (int i = 0; i < 4; i++)
#pragma unroll
        for (int j = 0; j < 32; j++) acc[i][j] = 0.f;

    for (int kk = 0; kk < 256; kk += 8) {
        __syncthreads();
        for (int i = tid; i < 8 * 1024; i += 256)
            ((float*)Bs)[i] = g_Et[kk * M_ + i];
        __syncthreads();
        float a[4][8];
#pragma unroll
        for (int i = 0; i < 4; i++)
#pragma unroll
            for (int k = 0; k < 8; k++)
                a[i][k] = g_cur[(size_t)(row0 + i) * D_ + kk + k];
#pragma unroll
        for (int j = 0; j < 32; j++) {
            float bb[8];
#pragma unroll
            for (int k = 0; k < 8; k++) bb[k] = Bs[k][j * 32 + lane];
#pragma unroll
            for (int i = 0; i < 4; i++) {
                float p = a[i][0] * bb[0];
#pragma unroll
                for (int k = 1; k < 8; k++) p = fmaf(a[i][k], bb[k], p);
                acc[i][j] += p;
            }
        }
    }

    float en[32];
#pragma unroll
    for (int j = 0; j < 32; j++) en[j] = g_en[j * 32 + lane];
#pragma unroll
    for (int i = 0; i < 4; i++)
#pragma unroll
        for (int j = 0; j < 32; j++)
            acc[i][j] = -((cn[i] + en[j]) - 2.f * acc[i][j]);   // matches ref op order

    // pass 1: hard argmax (histogram) + row max
    float rmax[4];
#pragma unroll
    for (int i = 0; i < 4; i++) {
        float mv = acc[i][0]; int mi = lane;
#pragma unroll
        for (int j = 1; j < 32; j++)
            if (acc[i][j] > mv) { mv = acc[i][j]; mi = j * 32 + lane; }
#pragma unroll
        for (int off = 16; off; off >>= 1) {
            float ov = __shfl_xor_sync(0xffffffffu, mv, off);
            int   oi = __shfl_xor_sync(0xffffffffu, mi, off);
            if (ov > mv || (ov == mv && oi < mi)) { mv = ov; mi = oi; }
        }
        rmax[i] = mv;
        if (lane == 0) atomicAdd(&g_hist[mi], 1);
    }

    // pass 2: softmax denominators
    float z[4];
#pragma unroll
    for (int i = 0; i < 4; i++) {
        float s = 0.f;
#pragma unroll
        for (int j = 0; j < 32; j++) s += __expf(acc[i][j] - rmax[i]);
#pragma unroll
        for (int off = 16; off; off >>= 1) s += __shfl_xor_sync(0xffffffffu, s, off);
        z[i] = s;
    }

    // pass 3: softmax column sums
#pragma unroll
    for (int j = 0; j < 32; j++) {
        float cs = 0.f;
#pragma unroll
        for (int i = 0; i < 4; i++)
            cs += __expf(acc[i][j] - rmax[i]) / z[i];
        atomicAdd(&s_avg[j * 32 + lane], cs);
    }

    // pass 4: gumbel argmax
#pragma unroll
    for (int i = 0; i < 4; i++) {
        int row = row0 + i;
        const float* up = gu + (size_t)row * M_;
        float mv = -3.4e38f; int mi = 0;
#pragma unroll
        for (int j = 0; j < 32; j++) {
            float u = up[j * 32 + lane];
            u = fminf(fmaxf(u, 1e-10f), 0.99999990f);
            float t = neg_log_acc(u);          // -log(u), fast-math safe
            float v = acc[i][j] - logf(t);     // dm + (-log(-log u))
            if (v > mv) { mv = v; mi = j * 32 + lane; }
        }
#pragma unroll
        for (int off = 16; off; off >>= 1) {
            float ov = __shfl_xor_sync(0xffffffffu, mv, off);
            int   oi = __shfl_xor_sync(0xffffffffu, mi, off);
            if (ov > mv || (ov == mv && oi < mi)) { mv = ov; mi = oi; }
        }
        if (lane == 0) { g_idx[row] = mi; dout[OFF_IND + row] = (float)mi; }
    }

    __syncthreads();
    for (int m = tid; m < M_; m += 256) atomicAdd(&g_avg[m], s_avg[m]);
}

__global__ void k_perp(float* __restrict__ dout) {
    __shared__ float red[1024];
    int m = threadIdx.x;
    float p = (float)g_hist[m] / 32768.f;
    red[m] = -p * log2f(p + 1e-10f);
    __syncthreads();
    for (int st = 512; st > 0; st >>= 1) {
        if (m < st) red[m] += red[m + st];
        __syncthreads();
    }
    if (m == 0) dout[OFF_CP] = red[0];
    __syncthreads();
    float q = g_avg[m] / 32768.f;
    red[m] = -q * log2f(q + 1e-10f);
    __syncthreads();
    for (int st = 512; st > 0; st >>= 1) {
        if (m < st) red[m] += red[m + st];
        __syncthreads();
    }
    if (m == 0) dout[OFF_PP] = red[0];
}

extern "C" void kernel_launch(void* const* d_in, const int* in_sizes, int n_in,
                              void* d_out, int out_size) {
    const float* x     = (const float*)d_in[0];
    const float* noise = (const float*)d_in[1];
    const float* gu    = (const float*)d_in[2];
    const int*   epo   = (const int*)d_in[3];
    const float* emb   = (const float*)d_in[4];
    const float* wctx  = (const float*)d_in[5];
    const float* wf1   = (const float*)d_in[6];
    const float* a1    = (const float*)d_in[7];
    const float* wf2   = (const float*)d_in[8];
    const float* a2    = (const float*)d_in[9];
    float* out = (float*)d_out;

    k_init<<<1, 1024>>>();
    k_scale<<<dim3(64, B_), 256>>>(x);
    k_coef<<<1, 32>>>(epo);
    k_prep<<<256, 256>>>(wctx, wf1, wf2, emb);
    k_ctxn<<<dim3((L_ + 31) / 32, D_ / 32, B_), dim3(32, 32)>>>(x, noise);
    k_conv<<<dim3(T_ / 128, D_ / 128, B_), 256>>>();
    k_fuse<0><<<dim3(BT_ / 128, D_ / 128), 256>>>(x, a1, out);
    k_dist<<<BT_ / 32, 256>>>(gu, out);
    k_perp<<<1, 1024>>>(out);
    k_fuse<1><<<dim3(BT_ / 128, D_ / 128), 256>>>(emb, a2, out);
}

// round 6
// speedup vs baseline: 1.0184x; 1.0184x over previous
#include <cuda_runtime.h>
#include <math.h>
#include <stdint.h>

#define B_   8
#define T_   4096
#define D_   256
#define M_   1024
#define CTX_ 7
#define L_   4102
#define BT_  32768
#define KC_  1792

#define OFF_CP  8388608
#define OFF_PP  8388609
#define OFF_IND 8388610

__device__ float g_ctxn[B_ * D_ * L_];
__device__ float g_ctxout[B_ * D_ * T_];
__device__ float g_cur[BT_ * D_];
__device__ float g_wt1[512 * D_];
__device__ float g_wt2[512 * D_];
__device__ float g_Et[D_ * M_];
__device__ float g_en[M_];
__device__ float g_ssum[B_];
__device__ float g_coef[B_];
__device__ int   g_idx[BT_];
__device__ int   g_hist[M_];
__device__ float g_avg[M_];

__device__ __forceinline__ float prelu_f(float v, float a) { return v >= 0.f ? v : a * v; }

__device__ __forceinline__ float neg_log_acc(float u) {
    if (u > 0.9f) {
        float d = 1.0f - u;
        return d * (1.f + d * (0.5f + d * (0.33333334f + d * (0.25f + d * (0.2f + d * 0.16666667f)))));
    }
    return -logf(u);
}

// ---- tf32 split + mma.sync (legacy tensor path; compiles under base sm_103) ----
__device__ __forceinline__ void tf32_split(float x, uint32_t& h, uint32_t& l) {
    uint32_t hu;
    asm("cvt.rna.tf32.f32 %0, %1;" : "=r"(hu) : "f"(x));
    float hf = __uint_as_float(hu);
    asm("cvt.rna.tf32.f32 %0, %1;" : "=r"(l) : "f"(x - hf));
    h = hu;
}
__device__ __forceinline__ void mma1688(float* d, const uint32_t* a, const uint32_t* b) {
    asm volatile(
        "mma.sync.aligned.m16n8k8.row.col.f32.tf32.tf32.f32 "
        "{%0,%1,%2,%3}, {%4,%5,%6,%7}, {%8,%9}, {%0,%1,%2,%3};"
        : "+f"(d[0]), "+f"(d[1]), "+f"(d[2]), "+f"(d[3])
        : "r"(a[0]), "r"(a[1]), "r"(a[2]), "r"(a[3]), "r"(b[0]), "r"(b[1]));
}

// ---------------- small kernels ----------------
__global__ void k_init() {
    int i = threadIdx.x;
    g_hist[i] = 0; g_avg[i] = 0.f;
    if (i < B_) g_ssum[i] = 0.f;
}

__global__ void k_scale(const float* __restrict__ x) {
    int b = blockIdx.y;
    const float* xb = x + (size_t)b * T_ * D_;
    const int n = (T_ - 1) * D_;
    float s = 0.f;
    for (int i = blockIdx.x * blockDim.x + threadIdx.x; i < n; i += gridDim.x * blockDim.x) {
        float v = xb[i]; s += v * v;
    }
    __shared__ float red[256];
    red[threadIdx.x] = s; __syncthreads();
    for (int st = 128; st > 0; st >>= 1) {
        if (threadIdx.x < st) red[threadIdx.x] += red[threadIdx.x + st];
        __syncthreads();
    }
    if (threadIdx.x == 0) atomicAdd(&g_ssum[b], red[0]);
}

__global__ void k_coef(const int* __restrict__ epo_i) {
    int b = threadIdx.x;
    if (b >= B_) return;
    int ei = *epo_i;
    double ef = (ei >= 0 && ei <= 1000000) ? (double)ei : (double)__int_as_float(ei);
    double mean = (double)g_ssum[b] / (double)(D_ * L_);
    g_coef[b] = (float)(0.5 * exp2(-ef / 10.0) * sqrt(mean));
}

__global__ void k_prep(const float* __restrict__ wf1, const float* __restrict__ wf2,
                       const float* __restrict__ emb) {
    int tid = blockIdx.x * blockDim.x + threadIdx.x;
    int stride = gridDim.x * blockDim.x;
    for (int i = tid; i < 512 * D_; i += stride) {
        int c = i / D_, o = i % D_;
        g_wt1[i] = wf1[o * 512 + c];
        g_wt2[i] = wf2[o * 512 + c];
    }
    for (int i = tid; i < D_ * M_; i += stride) {
        int d = i / M_, m = i % M_;
        g_Et[i] = emb[m * D_ + d];
    }
    int w = tid >> 5, lane = tid & 31;
    if (w < M_) {
        const float* er = emb + (size_t)w * D_;
        double s = 0.0;
        for (int d = lane; d < D_; d += 32) { double v = (double)er[d]; s += v * v; }
        for (int off = 16; off; off >>= 1) s += __shfl_xor_sync(0xffffffffu, s, off);
        if (lane == 0) g_en[w] = (float)s;
    }
}

__global__ void k_ctxn(const float* __restrict__ x, const float* __restrict__ noise) {
    __shared__ float xs[32][33];
    int b = blockIdx.z, bd = blockIdx.y * 32, bj = blockIdx.x * 32;
    int t = bj + threadIdx.y - CTX_;
    float v = 0.f;
    if (t >= 0 && t < T_ - 1)
        v = x[((size_t)b * T_ + t) * D_ + bd + threadIdx.x];
    xs[threadIdx.y][threadIdx.x] = v;
    __syncthreads();
    int j = bj + threadIdx.x;
    if (j < L_) {
        int d = bd + threadIdx.y;
        int off = (b * D_ + d) * L_ + j;
        g_ctxn[off] = xs[threadIdx.x][threadIdx.y] + g_coef[b] * noise[off];
    }
}

// ---------------- conv as 3xTF32 mma.sync GEMM ----------------
// Per CTA: C[128 o, 128 t] = sum_k W[o,k] Z[k,t], K=1792 in chunks of 32.
// 8 warps in 2(m)x4(n); warp tile 64x32 via m16n8k8 fragments.
__global__ __launch_bounds__(256) void k_convM(const float* __restrict__ wctx) {
    __shared__ float As[128][36];   // [m][k] pitch 36 -> conflict-free frag loads
    __shared__ float Bs[128][36];   // [n(t)][k]
    int tid = threadIdx.x, wid = tid >> 5, lane = tid & 31;
    int bn = blockIdx.x * 128, bm = blockIdx.y * 128, b = blockIdx.z;
    const float* ctxn_b = g_ctxn + (size_t)b * D_ * L_;
    int wm = wid >> 2, wn = wid & 3;
    int gr = lane >> 2, ctid = lane & 3;

    float acc[4][4][4];
#pragma unroll
    for (int i = 0; i < 4; i++)
#pragma unroll
        for (int j = 0; j < 4; j++)
#pragma unroll
            for (int r = 0; r < 4; r++) acc[i][j][r] = 0.f;

    int arow = tid >> 1, akg = (tid & 1) * 16;
    int bt = tid & 127, bk0 = tid >> 7;   // 0..1

    for (int kk = 0; kk < KC_; kk += 32) {
        __syncthreads();
        const float* ar = wctx + (size_t)(bm + arow) * KC_ + kk + akg;
#pragma unroll
        for (int q = 0; q < 4; q++)
            *(float4*)&As[arow][akg + q * 4] = *(const float4*)(ar + q * 4);
#pragma unroll
        for (int p = 0; p < 16; p++) {
            int k = bk0 + p * 2;
            int c = kk + k;
            int ci = c / CTX_, ck = c - ci * CTX_;
            Bs[bt][k] = ctxn_b[ci * L_ + bn + bt + ck];
        }
        __syncthreads();
#pragma unroll
        for (int ks = 0; ks < 4; ks++) {
            int k0 = ks * 8;
            uint32_t aH[4][4], aL[4][4];
#pragma unroll
            for (int mf = 0; mf < 4; mf++) {
                int r0 = wm * 64 + mf * 16;
                tf32_split(As[r0 + gr][k0 + ctid],          aH[mf][0], aL[mf][0]);
                tf32_split(As[r0 + gr + 8][k0 + ctid],      aH[mf][1], aL[mf][1]);
                tf32_split(As[r0 + gr][k0 + ctid + 4],      aH[mf][2], aL[mf][2]);
                tf32_split(As[r0 + gr + 8][k0 + ctid + 4],  aH[mf][3], aL[mf][3]);
            }
            uint32_t bH[4][2], bL[4][2];
#pragma unroll
            for (int nf = 0; nf < 4; nf++) {
                int n0 = wn * 32 + nf * 8;
                tf32_split(Bs[n0 + gr][k0 + ctid],     bH[nf][0], bL[nf][0]);
                tf32_split(Bs[n0 + gr][k0 + ctid + 4], bH[nf][1], bL[nf][1]);
            }
#pragma unroll
            for (int mf = 0; mf < 4; mf++)
#pragma unroll
                for (int nf = 0; nf < 4; nf++) {
                    mma1688(acc[mf][nf], aH[mf], bL[nf]);
                    mma1688(acc[mf][nf], aL[nf == 0 ? mf : mf], bH[nf]);
                    mma1688(acc[mf][nf], aH[mf], bH[nf]);
                }
        }
    }
    float* outb = g_ctxout + (size_t)b * D_ * T_;
#pragma unroll
    for (int mf = 0; mf < 4; mf++) {
        int o0 = bm + wm * 64 + mf * 16 + gr;
#pragma unroll
        for (int nf = 0; nf < 4; nf++) {
            int t0 = bn + wn * 32 + nf * 8 + 2 * ctid;
            *(float2*)&outb[(size_t)o0 * T_ + t0]       = make_float2(acc[mf][nf][0], acc[mf][nf][1]);
            *(float2*)&outb[(size_t)(o0 + 8) * T_ + t0] = make_float2(acc[mf][nf][2], acc[mf][nf][3]);
        }
    }
}

// ---------------- fuse GEMMs (SIMT fp32, proven) ----------------
template<int WHICH>
__global__ __launch_bounds__(256) void k_fuse(const float* __restrict__ rowsrc,
                                              const float* __restrict__ pa,
                                              float* __restrict__ outp) {
    __shared__ float As[16][128];
    __shared__ float Bs[16][132];
    __shared__ int idxS[128];
    int tid = threadIdx.x;
    int tok0 = blockIdx.x * 128;
    int b = tok0 >> 12, t0 = tok0 & (T_ - 1);
    int bm = blockIdx.y * 128;
    int tx = tid & 15, ty = tid >> 4;
    if (WHICH == 1 && tid < 128) idxS[tid] = g_idx[tok0 + tid];
    float acc[8][8];
#pragma unroll
    for (int i = 0; i < 8; i++)
#pragma unroll
        for (int j = 0; j < 8; j++) acc[i][j] = 0.f;
    const float* ctxoutb = g_ctxout + (size_t)b * D_ * T_;
    const float* W = (WHICH == 0) ? g_wt1 : g_wt2;
    float* optr = (WHICH == 0) ? g_cur : outp;
    int lA_k = tid >> 4, lA_m = (tid & 15) << 3;
    int xn = tid >> 1, xk = (tid & 1) << 3;
    int cn_ = tid & 127, ck0 = tid >> 7;
    __syncthreads();
    for (int kk = 0; kk < 512; kk += 16) {
        *(float4*)&As[lA_k][lA_m]     = *(const float4*)&W[(kk + lA_k) * D_ + bm + lA_m];
        *(float4*)&As[lA_k][lA_m + 4] = *(const float4*)&W[(kk + lA_k) * D_ + bm + lA_m + 4];
        if (kk < 256) {
            const float* rp;
            if (WHICH == 0) rp = rowsrc + (size_t)(tok0 + xn) * D_ + kk + xk;
            else            rp = rowsrc + (size_t)idxS[xn] * D_ + kk + xk;
            float4 v0 = *(const float4*)rp;
            float4 v1 = *(const float4*)(rp + 4);
            Bs[xk + 0][xn] = v0.x; Bs[xk + 1][xn] = v0.y;
            Bs[xk + 2][xn] = v0.z; Bs[xk + 3][xn] = v0.w;
            Bs[xk + 4][xn] = v1.x; Bs[xk + 5][xn] = v1.y;
            Bs[xk + 6][xn] = v1.z; Bs[xk + 7][xn] = v1.w;
        } else {
#pragma unroll
            for (int p = 0; p < 8; p++) {
                int k = ck0 + p * 2;
                Bs[k][cn_] = ctxoutb[(kk - 256 + k) * T_ + t0 + cn_];
            }
        }
        __syncthreads();
#pragma unroll
        for (int k = 0; k < 16; k++) {
            float a[8], bb[8];
            *(float4*)&a[0]  = *(float4*)&As[k][ty * 8];
            *(float4*)&a[4]  = *(float4*)&As[k][ty * 8 + 4];
            *(float4*)&bb[0] = *(float4*)&Bs[k][tx * 8];
            *(float4*)&bb[4] = *(float4*)&Bs[k][tx * 8 + 4];
#pragma unroll
            for (int i = 0; i < 8; i++)
#pragma unroll
                for (int j = 0; j < 8; j++) acc[i][j] = fmaf(a[i], bb[j], acc[i][j]);
        }
        __syncthreads();
    }
    float av = *pa;
#pragma unroll
    for (int j = 0; j < 8; j++) {
        int tok = tok0 + tx * 8 + j;
        float* dst = &optr[(size_t)tok * D_ + bm + ty * 8];
        *(float4*)dst = make_float4(prelu_f(acc[0][j], av), prelu_f(acc[1][j], av),
                                    prelu_f(acc[2][j], av), prelu_f(acc[3][j], av));
        *(float4*)(dst + 4) = make_float4(prelu_f(acc[4][j], av), prelu_f(acc[5][j], av),
                                          prelu_f(acc[6][j], av), prelu_f(acc[7][j], av));
    }
}

// ---------------- dist + softmax stats + argmaxes (proven) ----------------
__global__ __launch_bounds__(256) void k_dist(const float* __restrict__ gu,
                                              float* __restrict__ dout) {
    __shared__ float Bs[8][1024];
    __shared__ float s_avg[1024];
    int tid = threadIdx.x;
    int w = tid >> 5, lane = tid & 31;
    int r0 = blockIdx.x * 32;
    int row0 = r0 + w * 4;

    for (int i = tid; i < M_; i += 256) s_avg[i] = 0.f;

    float cn[4];
#pragma unroll
    for (int i = 0; i < 4; i++) {
        const float* cr = g_cur + (size_t)(row0 + i) * D_;
        float s = 0.f;
#pragma unroll
        for (int q = 0; q < 8; q++) { float v = cr[lane + q * 32]; s += v * v; }
#pragma unroll
        for (int off = 16; off; off >>= 1) s += __shfl_xor_sync(0xffffffffu, s, off);
        cn[i] = s;
    }

    float acc[4][32];
#pragma unroll
    for (int i = 0; i < 4; i++)
#pragma unroll
        for (int j = 0; j < 32; j++) acc[i][j] = 0.f;

    for (int kk = 0; kk < 256; kk += 8) {
        __syncthreads();
        for (int i = tid; i < 8 * 1024; i += 256)
            ((float*)Bs)[i] = g_Et[kk * M_ + i];
        __syncthreads();
        float a[4][8];
#pragma unroll
        for (int i = 0; i < 4; i++)
#pragma unroll
            for (int k = 0; k < 8; k++)
                a[i][k] = g_cur[(size_t)(row0 + i) * D_ + kk + k];
#pragma unroll
        for (int j = 0; j < 32; j++) {
            float bb[8];
#pragma unroll
            for (int k = 0; k < 8; k++) bb[k] = Bs[k][j * 32 + lane];
#pragma unroll
            for (int i = 0; i < 4; i++) {
                float p = a[i][0] * bb[0];
#pragma unroll
                for (int k = 1; k < 8; k++) p = fmaf(a[i][k], bb[k], p);
                acc[i][j] += p;
            }
        }
    }

    float en[32];
#pragma unroll
    for (int j = 0; j < 32; j++) en[j] = g_en[j * 32 + lane];
#pragma unroll
    for (int i = 0; i < 4; i++)
#pragma unroll
        for (int j = 0; j < 32; j++)
            acc[i][j] = -((cn[i] + en[j]) - 2.f * acc[i][j]);

    float rmax[4];
#pragma unroll
    for (int i = 0; i < 4; i++) {
        float mv = acc[i][0]; int mi = lane;
#pragma unroll
        for (int j = 1; j < 32; j++)
            if (acc[i][j] > mv) { mv = acc[i][j]; mi = j * 32 + lane; }
#pragma unroll
        for (int off = 16; off; off >>= 1) {
            float ov = __shfl_xor_sync(0xffffffffu, mv, off);
            int   oi = __shfl_xor_sync(0xffffffffu, mi, off);
            if (ov > mv || (ov == mv && oi < mi)) { mv = ov; mi = oi; }
        }
        rmax[i] = mv;
        if (lane == 0) atomicAdd(&g_hist[mi], 1);
    }

    float z[4];
#pragma unroll
    for (int i = 0; i < 4; i++) {
        float s = 0.f;
#pragma unroll
        for (int j = 0; j < 32; j++) s += __expf(acc[i][j] - rmax[i]);
#pragma unroll
        for (int off = 16; off; off >>= 1) s += __shfl_xor_sync(0xffffffffu, s, off);
        z[i] = s;
    }

#pragma unroll
    for (int j = 0; j < 32; j++) {
        float cs = 0.f;
#pragma unroll
        for (int i = 0; i < 4; i++)
            cs += __expf(acc[i][j] - rmax[i]) / z[i];
        atomicAdd(&s_avg[j * 32 + lane], cs);
    }

#pragma unroll
    for (int i = 0; i < 4; i++) {
        int row = row0 + i;
        const float* up = gu + (size_t)row * M_;
        float mv = -3.4e38f; int mi = 0;
#pragma unroll
        for (int j = 0; j < 32; j++) {
            float u = up[j * 32 + lane];
            u = fminf(fmaxf(u, 1e-10f), 0.99999990f);
            float t = neg_log_acc(u);
            float v = acc[i][j] - logf(t);
            if (v > mv) { mv = v; mi = j * 32 + lane; }
        }
#pragma unroll
        for (int off = 16; off; off >>= 1) {
            float ov = __shfl_xor_sync(0xffffffffu, mv, off);
            int   oi = __shfl_xor_sync(0xffffffffu, mi, off);
            if (ov > mv || (ov == mv && oi < mi)) { mv = ov; mi = oi; }
        }
        if (lane == 0) { g_idx[row] = mi; dout[OFF_IND + row] = (float)mi; }
    }

    __syncthreads();
    for (int m = tid; m < M_; m += 256) atomicAdd(&g_avg[m], s_avg[m]);
}

__global__ void k_perp(float* __restrict__ dout) {
    __shared__ float red[1024];
    int m = threadIdx.x;
    float p = (float)g_hist[m] / 32768.f;
    red[m] = -p * log2f(p + 1e-10f);
    __syncthreads();
    for (int st = 512; st > 0; st >>= 1) {
        if (m < st) red[m] += red[m + st];
        __syncthreads();
    }
    if (m == 0) dout[OFF_CP] = red[0];
    __syncthreads();
    float q = g_avg[m] / 32768.f;
    red[m] = -q * log2f(q + 1e-10f);
    __syncthreads();
    for (int st = 512; st > 0; st >>= 1) {
        if (m < st) red[m] += red[m + st];
        __syncthreads();
    }
    if (m == 0) dout[OFF_PP] = red[0];
}

extern "C" void kernel_launch(void* const* d_in, const int* in_sizes, int n_in,
                              void* d_out, int out_size) {
    const float* x     = (const float*)d_in[0];
    const float* noise = (const float*)d_in[1];
    const float* gu    = (const float*)d_in[2];
    const int*   epo   = (const int*)d_in[3];
    const float* emb   = (const float*)d_in[4];
    const float* wctx  = (const float*)d_in[5];
    const float* wf1   = (const float*)d_in[6];
    const float* a1    = (const float*)d_in[7];
    const float* wf2   = (const float*)d_in[8];
    const float* a2    = (const float*)d_in[9];
    float* out = (float*)d_out;

    k_init<<<1, 1024>>>();
    k_scale<<<dim3(64, B_), 256>>>(x);
    k_coef<<<1, 32>>>(epo);
    k_prep<<<256, 256>>>(wf1, wf2, emb);
    k_ctxn<<<dim3((L_ + 31) / 32, D_ / 32, B_), dim3(32, 32)>>>(x, noise);
    k_convM<<<dim3(T_ / 128, D_ / 128, B_), 256>>>(wctx);
    k_fuse<0><<<dim3(BT_ / 128, D_ / 128), 256>>>(x, a1, out);
    k_dist<<<BT_ / 32, 256>>>(gu, out);
    k_perp<<<1, 1024>>>(out);
    k_fuse<1><<<dim3(BT_ / 128, D_ / 128), 256>>>(emb, a2, out);
}

// round 7
// speedup vs baseline: 1.0665x; 1.0472x over previous
#include <cuda_runtime.h>
#include <cuda_fp16.h>
#include <math.h>
#include <stdint.h>

#define B_   8
#define T_   4096
#define D_   256
#define M_   1024
#define CTX_ 7
#define L_   4102
#define BT_  32768
#define KC_  1792

#define OFF_CP  8388608
#define OFF_PP  8388609
#define OFF_IND 8388610

__device__ float g_ctxn[B_ * D_ * L_];
__device__ float g_ctxout[B_ * D_ * T_];
__device__ float g_cur[BT_ * D_];
__device__ float g_wt1[512 * D_];
__device__ float g_wt2[512 * D_];
__device__ float g_Et[D_ * M_];
__device__ float g_en[M_];
__device__ float g_part[B_][64];
__device__ float g_coef[B_];
__device__ int   g_idx[BT_];
__device__ int   g_hist[M_];
__device__ float g_avg[M_];

__device__ __forceinline__ float prelu_f(float v, float a) { return v >= 0.f ? v : a * v; }

__device__ __forceinline__ float neg_log_acc(float u) {
    if (u > 0.9f) {
        float d = 1.0f - u;
        return d * (1.f + d * (0.5f + d * (0.33333334f + d * (0.25f + d * (0.2f + d * 0.16666667f)))));
    }
    return -logf(u);
}

// ---- fp16 split + legacy mma.sync m16n8k16 ----
__device__ __forceinline__ void f16_split(float x, uint32_t& hlo_slot_h, uint32_t& hlo_slot_l,
                                          int hi_half) {
    // helper not used; see inline staging
}
__device__ __forceinline__ uint32_t pack_h2(__half a, __half b) {
    __half2 h = __halves2half2(a, b);
    return *(uint32_t*)&h;
}
__device__ __forceinline__ void mma16816(float* d, const uint32_t* a, const uint32_t* b) {
    asm volatile(
        "mma.sync.aligned.m16n8k16.row.col.f32.f16.f16.f32 "
        "{%0,%1,%2,%3}, {%4,%5,%6,%7}, {%8,%9}, {%0,%1,%2,%3};"
        : "+f"(d[0]), "+f"(d[1]), "+f"(d[2]), "+f"(d[3])
        : "r"(a[0]), "r"(a[1]), "r"(a[2]), "r"(a[3]), "r"(b[0]), "r"(b[1]));
}

// ---------------- small kernels ----------------
__global__ void k_scale(const float* __restrict__ x) {
    int b = blockIdx.y;
    const float* xb = x + (size_t)b * T_ * D_;
    const int n = (T_ - 1) * D_;
    float s = 0.f;
    for (int i = blockIdx.x * blockDim.x + threadIdx.x; i < n; i += gridDim.x * blockDim.x) {
        float v = xb[i]; s += v * v;
    }
    __shared__ float red[256];
    red[threadIdx.x] = s; __syncthreads();
    for (int st = 128; st > 0; st >>= 1) {
        if (threadIdx.x < st) red[threadIdx.x] += red[threadIdx.x + st];
        __syncthreads();
    }
    if (threadIdx.x == 0) g_part[b][blockIdx.x] = red[0];
}

__global__ void k_coef(const int* __restrict__ epo_i) {
    int w = threadIdx.x >> 5, lane = threadIdx.x & 31;
    if (w >= B_) return;
    float s = g_part[w][lane] + g_part[w][lane + 32];
    for (int off = 16; off; off >>= 1) s += __shfl_xor_sync(0xffffffffu, s, off);
    if (lane == 0) {
        int ei = *epo_i;
        double ef = (ei >= 0 && ei <= 1000000) ? (double)ei : (double)__int_as_float(ei);
        double mean = (double)s / (double)(D_ * L_);
        g_coef[w] = (float)(0.5 * exp2(-ef / 10.0) * sqrt(mean));
    }
}

__global__ void k_ctxn(const float* __restrict__ x, const float* __restrict__ noise) {
    __shared__ float xs[32][33];
    int b = blockIdx.z, bd = blockIdx.y * 32, bj = blockIdx.x * 32;
    int t = bj + threadIdx.y - CTX_;
    float v = 0.f;
    if (t >= 0 && t < T_ - 1)
        v = x[((size_t)b * T_ + t) * D_ + bd + threadIdx.x];
    xs[threadIdx.y][threadIdx.x] = v;
    __syncthreads();
    int j = bj + threadIdx.x;
    if (j < L_) {
        int d = bd + threadIdx.y;
        int off = (b * D_ + d) * L_ + j;
        g_ctxn[off] = xs[threadIdx.x][threadIdx.y] + g_coef[b] * noise[off];
    }
}

// ---------------- conv as fp16x3 mma.sync GEMM ----------------
// C[128 o, 128 t] = sum_k W[o,k] Z[k,t], K=1792 in chunks of 32 (2 x k16 mma steps).
// Operands pre-split into half2-packed smem; pitch 20 words -> conflict-free frags.
__global__ __launch_bounds__(256) void k_convM(const float* __restrict__ wctx) {
    __shared__ uint32_t AH[128][20], AL[128][20], BH[128][20], BL[128][20];
    int tid = threadIdx.x, wid = tid >> 5, lane = tid & 31;
    int bn = blockIdx.x * 128, bm = blockIdx.y * 128, b = blockIdx.z;
    const float* ctxn_b = g_ctxn + (size_t)b * D_ * L_;
    int wm = wid >> 2, wn = wid & 3;
    int gr = lane >> 2, ctid = lane & 3;

    float acc[4][4][4];
#pragma unroll
    for (int i = 0; i < 4; i++)
#pragma unroll
        for (int j = 0; j < 4; j++)
#pragma unroll
            for (int r = 0; r < 4; r++) acc[i][j][r] = 0.f;

    int arow = tid >> 1;
    int akg  = (tid & 1) * 16;   // float k offset within chunk
    int acp  = (tid & 1) * 8;    // half2 col base
    int bt   = tid & 127;
    int bkh  = (tid >> 7) * 16;
    int bcp  = (tid >> 7) * 8;

    for (int kk = 0; kk < KC_; kk += 32) {
        __syncthreads();
        // stage A (weights)
        {
            const float* ar = wctx + (size_t)(bm + arow) * KC_ + kk + akg;
#pragma unroll
            for (int p = 0; p < 8; p++) {
                float x0 = ar[2 * p], x1 = ar[2 * p + 1];
                __half h0 = __float2half_rn(x0), h1 = __float2half_rn(x1);
                __half l0 = __float2half_rn(x0 - __half2float(h0));
                __half l1 = __float2half_rn(x1 - __half2float(h1));
                AH[arow][acp + p] = pack_h2(h0, h1);
                AL[arow][acp + p] = pack_h2(l0, l1);
            }
        }
        // stage B (conv windows Z[k,t] = ctxn[ci, t+ck], k = ci*7+ck)
        {
#pragma unroll
            for (int p = 0; p < 8; p++) {
                int c0 = kk + bkh + 2 * p;
                int ci0 = c0 / CTX_, ck0 = c0 - ci0 * CTX_;
                int c1 = c0 + 1;
                int ci1 = c1 / CTX_, ck1 = c1 - ci1 * CTX_;
                float x0 = ctxn_b[ci0 * L_ + bn + bt + ck0];
                float x1 = ctxn_b[ci1 * L_ + bn + bt + ck1];
                __half h0 = __float2half_rn(x0), h1 = __float2half_rn(x1);
                __half l0 = __float2half_rn(x0 - __half2float(h0));
                __half l1 = __float2half_rn(x1 - __half2float(h1));
                BH[bt][bcp + p] = pack_h2(h0, h1);
                BL[bt][bcp + p] = pack_h2(l0, l1);
            }
        }
        __syncthreads();
#pragma unroll
        for (int ks = 0; ks < 2; ks++) {
            int kp = ks * 8;
            uint32_t aH[4][4], aL[4][4];
#pragma unroll
            for (int mf = 0; mf < 4; mf++) {
                int r0 = wm * 64 + mf * 16;
                aH[mf][0] = AH[r0 + gr][kp + ctid];
                aH[mf][1] = AH[r0 + gr + 8][kp + ctid];
                aH[mf][2] = AH[r0 + gr][kp + ctid + 4];
                aH[mf][3] = AH[r0 + gr + 8][kp + ctid + 4];
                aL[mf][0] = AL[r0 + gr][kp + ctid];
                aL[mf][1] = AL[r0 + gr + 8][kp + ctid];
                aL[mf][2] = AL[r0 + gr][kp + ctid + 4];
                aL[mf][3] = AL[r0 + gr + 8][kp + ctid + 4];
            }
#pragma unroll
            for (int nf = 0; nf < 4; nf++) {
                int n0 = wn * 32 + nf * 8;
                uint32_t bh[2], bl[2];
                bh[0] = BH[n0 + gr][kp + ctid];
                bh[1] = BH[n0 + gr][kp + ctid + 4];
                bl[0] = BL[n0 + gr][kp + ctid];
                bl[1] = BL[n0 + gr][kp + ctid + 4];
#pragma unroll
                for (int mf = 0; mf < 4; mf++) {
                    mma16816(acc[mf][nf], aH[mf], bl);
                    mma16816(acc[mf][nf], aL[mf], bh);
                    mma16816(acc[mf][nf], aH[mf], bh);
                }
            }
        }
    }
    float* outb = g_ctxout + (size_t)b * D_ * T_;
#pragma unroll
    for (int mf = 0; mf < 4; mf++) {
        int o0 = bm + wm * 64 + mf * 16 + gr;
#pragma unroll
        for (int nf = 0; nf < 4; nf++) {
            int t0 = bn + wn * 32 + nf * 8 + 2 * ctid;
            *(float2*)&outb[(size_t)o0 * T_ + t0]       = make_float2(acc[mf][nf][0], acc[mf][nf][1]);
            *(float2*)&outb[(size_t)(o0 + 8) * T_ + t0] = make_float2(acc[mf][nf][2], acc[mf][nf][3]);
        }
    }
}

__global__ void k_prep(const float* __restrict__ wf1, const float* __restrict__ wf2,
                       const float* __restrict__ emb) {
    int tid = blockIdx.x * blockDim.x + threadIdx.x;
    int stride = gridDim.x * blockDim.x;
    if (tid < M_) { g_hist[tid] = 0; g_avg[tid] = 0.f; }
    for (int i = tid; i < 512 * D_; i += stride) {
        int c = i / D_, o = i % D_;
        g_wt1[i] = wf1[o * 512 + c];
        g_wt2[i] = wf2[o * 512 + c];
    }
    for (int i = tid; i < D_ * M_; i += stride) {
        int d = i / M_, m = i % M_;
        g_Et[i] = emb[m * D_ + d];
    }
    int w = tid >> 5, lane = tid & 31;
    if (w < M_) {
        const float* er = emb + (size_t)w * D_;
        double s = 0.0;
        for (int d = lane; d < D_; d += 32) { double v = (double)er[d]; s += v * v; }
        for (int off = 16; off; off >>= 1) s += __shfl_xor_sync(0xffffffffu, s, off);
        if (lane == 0) g_en[w] = (float)s;
    }
}

// ---------------- fuse GEMMs (SIMT fp32, proven) ----------------
template<int WHICH>
__global__ __launch_bounds__(256) void k_fuse(const float* __restrict__ rowsrc,
                                              const float* __restrict__ pa,
                                              float* __restrict__ outp) {
    __shared__ float As[16][128];
    __shared__ float Bs[16][132];
    __shared__ int idxS[128];
    int tid = threadIdx.x;
    int tok0 = blockIdx.x * 128;
    int b = tok0 >> 12, t0 = tok0 & (T_ - 1);
    int bm = blockIdx.y * 128;
    int tx = tid & 15, ty = tid >> 4;
    if (WHICH == 1 && tid < 128) idxS[tid] = g_idx[tok0 + tid];
    float acc[8][8];
#pragma unroll
    for (int i = 0; i < 8; i++)
#pragma unroll
        for (int j = 0; j < 8; j++) acc[i][j] = 0.f;
    const float* ctxoutb = g_ctxout + (size_t)b * D_ * T_;
    const float* W = (WHICH == 0) ? g_wt1 : g_wt2;
    float* optr = (WHICH == 0) ? g_cur : outp;
    int lA_k = tid >> 4, lA_m = (tid & 15) << 3;
    int xn = tid >> 1, xk = (tid & 1) << 3;
    int cn_ = tid & 127, ck0 = tid >> 7;
    __syncthreads();
    for (int kk = 0; kk < 512; kk += 16) {
        *(float4*)&As[lA_k][lA_m]     = *(const float4*)&W[(kk + lA_k) * D_ + bm + lA_m];
        *(float4*)&As[lA_k][lA_m + 4] = *(const float4*)&W[(kk + lA_k) * D_ + bm + lA_m + 4];
        if (kk < 256) {
            const float* rp;
            if (WHICH == 0) rp = rowsrc + (size_t)(tok0 + xn) * D_ + kk + xk;
            else            rp = rowsrc + (size_t)idxS[xn] * D_ + kk + xk;
            float4 v0 = *(const float4*)rp;
            float4 v1 = *(const float4*)(rp + 4);
            Bs[xk + 0][xn] = v0.x; Bs[xk + 1][xn] = v0.y;
            Bs[xk + 2][xn] = v0.z; Bs[xk + 3][xn] = v0.w;
            Bs[xk + 4][xn] = v1.x; Bs[xk + 5][xn] = v1.y;
            Bs[xk + 6][xn] = v1.z; Bs[xk + 7][xn] = v1.w;
        } else {
#pragma unroll
            for (int p = 0; p < 8; p++) {
                int k = ck0 + p * 2;
                Bs[k][cn_] = ctxoutb[(kk - 256 + k) * T_ + t0 + cn_];
            }
        }
        __syncthreads();
#pragma unroll
        for (int k = 0; k < 16; k++) {
            float a[8], bb[8];
            *(float4*)&a[0]  = *(float4*)&As[k][ty * 8];
            *(float4*)&a[4]  = *(float4*)&As[k][ty * 8 + 4];
            *(float4*)&bb[0] = *(float4*)&Bs[k][tx * 8];
            *(float4*)&bb[4] = *(float4*)&Bs[k][tx * 8 + 4];
#pragma unroll
            for (int i = 0; i < 8; i++)
#pragma unroll
                for (int j = 0; j < 8; j++) acc[i][j] = fmaf(a[i], bb[j], acc[i][j]);
        }
        __syncthreads();
    }
    float av = *pa;
#pragma unroll
    for (int j = 0; j < 8; j++) {
        int tok = tok0 + tx * 8 + j;
        float* dst = &optr[(size_t)tok * D_ + bm + ty * 8];
        *(float4*)dst = make_float4(prelu_f(acc[0][j], av), prelu_f(acc[1][j], av),
                                    prelu_f(acc[2][j], av), prelu_f(acc[3][j], av));
        *(float4*)(dst + 4) = make_float4(prelu_f(acc[4][j], av), prelu_f(acc[5][j], av),
                                          prelu_f(acc[6][j], av), prelu_f(acc[7][j], av));
    }
}

// ---------------- dist + softmax stats + argmaxes (proven) ----------------
__global__ __launch_bounds__(256) void k_dist(const float* __restrict__ gu,
                                              float* __restrict__ dout) {
    __shared__ float Bs[8][1024];
    __shared__ float s_avg[1024];
    int tid = threadIdx.x;
    int w = tid >> 5, lane = tid & 31;
    int r0 = blockIdx.x * 32;
    int row0 = r0 + w * 4;

    for (int i = tid; i < M_; i += 256) s_avg[i] = 0.f;

    float cn[4];
#pragma unroll
    for (int i = 0; i < 4; i++) {
        const float* cr = g_cur + (size_t)(row0 + i) * D_;
        float s = 0.f;
#pragma unroll
        for (int q = 0; q < 8; q++) { float v = cr[lane + q * 32]; s += v * v; }
#pragma unroll
        for (int off = 16; off; off >>= 1) s += __shfl_xor_sync(0xffffffffu, s, off);
        cn[i] = s;
    }

    float acc[4][32];
#pragma unroll
    for (int i = 0; i < 4; i++)
#pragma unroll
        for (int j = 0; j < 32; j++) acc[i][j] = 0.f;

    for (int kk = 0; kk < 256; kk += 8) {
        __syncthreads();
        for (int i = tid; i < 8 * 1024; i += 256)
            ((float*)Bs)[i] = g_Et[kk * M_ + i];
        __syncthreads();
        float a[4][8];
#pragma unroll
        for (int i = 0; i < 4; i++)
#pragma unroll
            for (int k = 0; k < 8; k++)
                a[i][k] = g_cur[(size_t)(row0 + i) * D_ + kk + k];
#pragma unroll
        for (int j = 0; j < 32; j++) {
            float bb[8];
#pragma unroll
            for (int k = 0; k < 8; k++) bb[k] = Bs[k][j * 32 + lane];
#pragma unroll
            for (int i = 0; i < 4; i++) {
                float p = a[i][0] * bb[0];
#pragma unroll
                for (int k = 1; k < 8; k++) p = fmaf(a[i][k], bb[k], p);
                acc[i][j] += p;
            }
        }
    }

    float en[32];
#pragma unroll
    for (int j = 0; j < 32; j++) en[j] = g_en[j * 32 + lane];
#pragma unroll
    for (int i = 0; i < 4; i++)
#pragma unroll
        for (int j = 0; j < 32; j++)
            acc[i][j] = -((cn[i] + en[j]) - 2.f * acc[i][j]);

    float rmax[4];
#pragma unroll
    for (int i = 0; i < 4; i++) {
        float mv = acc[i][0]; int mi = lane;
#pragma unroll
        for (int j = 1; j < 32; j++)
            if (acc[i][j] > mv) { mv = acc[i][j]; mi = j * 32 + lane; }
#pragma unroll
        for (int off = 16; off; off >>= 1) {
            float ov = __shfl_xor_sync(0xffffffffu, mv, off);
            int   oi = __shfl_xor_sync(0xffffffffu, mi, off);
            if (ov > mv || (ov == mv && oi < mi)) { mv = ov; mi = oi; }
        }
        rmax[i] = mv;
        if (lane == 0) atomicAdd(&g_hist[mi], 1);
    }

    float z[4];
#pragma unroll
    for (int i = 0; i < 4; i++) {
        float s = 0.f;
#pragma unroll
        for (int j = 0; j < 32; j++) s += __expf(acc[i][j] - rmax[i]);
#pragma unroll
        for (int off = 16; off; off >>= 1) s += __shfl_xor_sync(0xffffffffu, s, off);
        z[i] = s;
    }

#pragma unroll
    for (int j = 0; j < 32; j++) {
        float cs = 0.f;
#pragma unroll
        for (int i = 0; i < 4; i++)
            cs += __expf(acc[i][j] - rmax[i]) / z[i];
        atomicAdd(&s_avg[j * 32 + lane], cs);
    }

#pragma unroll
    for (int i = 0; i < 4; i++) {
        int row = row0 + i;
        const float* up = gu + (size_t)row * M_;
        float mv = -3.4e38f; int mi = 0;
#pragma unroll
        for (int j = 0; j < 32; j++) {
            float u = up[j * 32 + lane];
            u = fminf(fmaxf(u, 1e-10f), 0.99999990f);
            float t = neg_log_acc(u);
            float v = acc[i][j] - logf(t);
            if (v > mv) { mv = v; mi = j * 32 + lane; }
        }
#pragma unroll
        for (int off = 16; off; off >>= 1) {
            float ov = __shfl_xor_sync(0xffffffffu, mv, off);
            int   oi = __shfl_xor_sync(0xffffffffu, mi, off);
            if (ov > mv || (ov == mv && oi < mi)) { mv = ov; mi = oi; }
        }
        if (lane == 0) { g_idx[row] = mi; dout[OFF_IND + row] = (float)mi; }
    }

    __syncthreads();
    for (int m = tid; m < M_; m += 256) atomicAdd(&g_avg[m], s_avg[m]);
}

__global__ void k_perp(float* __restrict__ dout) {
    __shared__ float red[1024];
    int m = threadIdx.x;
    float p = (float)g_hist[m] / 32768.f;
    red[m] = -p * log2f(p + 1e-10f);
    __syncthreads();
    for (int st = 512; st > 0; st >>= 1) {
        if (m < st) red[m] += red[m + st];
        __syncthreads();
    }
    if (m == 0) dout[OFF_CP] = red[0];
    __syncthreads();
    float q = g_avg[m] / 32768.f;
    red[m] = -q * log2f(q + 1e-10f);
    __syncthreads();
    for (int st = 512; st > 0; st >>= 1) {
        if (m < st) red[m] += red[m + st];
        __syncthreads();
    }
    if (m == 0) dout[OFF_PP] = red[0];
}

extern "C" void kernel_launch(void* const* d_in, const int* in_sizes, int n_in,
                              void* d_out, int out_size) {
    const float* x     = (const float*)d_in[0];
    const float* noise = (const float*)d_in[1];
    const float* gu    = (const float*)d_in[2];
    const int*   epo   = (const int*)d_in[3];
    const float* emb   = (const float*)d_in[4];
    const float* wctx  = (const float*)d_in[5];
    const float* wf1   = (const float*)d_in[6];
    const float* a1    = (const float*)d_in[7];
    const float* wf2   = (const float*)d_in[8];
    const float* a2    = (const float*)d_in[9];
    float* out = (float*)d_out;

    k_scale<<<dim3(64, B_), 256>>>(x);
    k_coef<<<1, 256>>>(epo);
    k_ctxn<<<dim3((L_ + 31) / 32, D_ / 32, B_), dim3(32, 32)>>>(x, noise);
    k_convM<<<dim3(T_ / 128, D_ / 128, B_), 256>>>(wctx);   // launch index 3 -> ncu slot
    k_prep<<<256, 256>>>(wf1, wf2, emb);
    k_fuse<0><<<dim3(BT_ / 128, D_ / 128), 256>>>(x, a1, out);
    k_dist<<<BT_ / 32, 256>>>(gu, out);
    k_perp<<<1, 1024>>>(out);
    k_fuse<1><<<dim3(BT_ / 128, D_ / 128), 256>>>(emb, a2, out);
}